// round 16
// baseline (speedup 1.0000x reference)
#include <cuda_runtime.h>
#include <cuda_fp16.h>
#include <cstdint>

// ---------------- problem dims ----------------
#define NB 256
#define NS 256
#define ND 64
#define NH 1024
#define NG 4096
#define NT 32
#define BHE (NB*NH)

// ---------------- GEMM tiling (BM=32 -> 512 CTAs -> 3-4 CTAs/SM) ----------
#define BM 32
#define BN 64
#define BK 32                  // halves per stage; stage row = 64 bytes
#define NSLOT 6
#define LEAD 5
#define A_TILE_B 2048          // 32 rows x 64B
#define B_TILE_B 4096          // 64 rows x 64B
#define SLOT_B (A_TILE_B + B_TILE_B)   // 6144
#define SMEM_OFF 1024
#define SMEM_BYTES (SMEM_OFF + NSLOT*SLOT_B)   // 37888 -> 4 CTAs/SM by smem
#define A_STG 16384            // bytes per A' stage (256 rows x 64B)
#define B_STG 262144           // bytes per W' stage (4096 rows x 64B)

// ---------------- device scratch (stage-major, swizzled layouts) ----------
// A'/W' layout: [stage][row][32 halves], row = 64B, swizzle SW64 baked in.
__device__ __align__(128) __half g_Xh [NS*NB*ND];          // X': [t][2][256][32]
__device__ __align__(128) __half g_W0 [(size_t)NG*1088];   // W0': [34][4096][32]
__device__ __align__(128) __half g_W1 [(size_t)NG*2048];   // W1': [64][4096][32]
__device__ __align__(128) __half g_DW0[(size_t)NG*1024];   // DW0': [32][4096][32]
__device__ __align__(128) __half g_DW1[(size_t)NG*2048];   // DW1': [64][4096][32]
__device__ __align__(128) __half g_h0 [2*BHE];             // h0': pingpong [32][256][32]
__device__ __align__(128) __half g_h1 [2*BHE];
__device__ __align__(128) float  g_c0 [BHE];
__device__ __align__(128) float  g_c1 [BHE];
__device__ __align__(128) float  g_h1f[BHE];               // fp32 h1 (linear) for fc
__device__ __align__(128) float  g_pred[NB];

// ---------------- PTX helpers ----------------
__device__ __forceinline__ uint32_t smem_u32(const void* p){
    return (uint32_t)__cvta_generic_to_shared(p);
}
__device__ __forceinline__ uint32_t swz64(uint32_t off){   // SW64: XOR bits[5:4] by bits[8:7]
    return off ^ ((off >> 3) & 0x30);
}
__device__ __forceinline__ void ldsm_x4(uint32_t&r0,uint32_t&r1,uint32_t&r2,uint32_t&r3,uint32_t a){
    asm volatile("ldmatrix.sync.aligned.m8n8.x4.shared.b16 {%0,%1,%2,%3},[%4];\n"
        : "=r"(r0),"=r"(r1),"=r"(r2),"=r"(r3) : "r"(a));
}
__device__ __forceinline__ void mma16816(float* c,
    uint32_t a0,uint32_t a1,uint32_t a2,uint32_t a3,uint32_t b0,uint32_t b1){
    asm volatile("mma.sync.aligned.m16n8k16.row.col.f32.f16.f16.f32 "
        "{%0,%1,%2,%3},{%4,%5,%6,%7},{%8,%9},{%0,%1,%2,%3};\n"
        : "+f"(c[0]),"+f"(c[1]),"+f"(c[2]),"+f"(c[3])
        : "r"(a0),"r"(a1),"r"(a2),"r"(a3),"r"(b0),"r"(b1));
}
#define MBARRIER_INIT(addr, cnt) \
    asm volatile("mbarrier.init.shared.b64 [%0], %1;" :: "r"((uint32_t)(addr)), "r"((uint32_t)(cnt)) : "memory")
#define MBARRIER_WAIT_PARITY(addr, par) do { \
    uint32_t _mb = (uint32_t)(addr); uint32_t _p = (uint32_t)(par); uint32_t _done; \
    asm volatile("{\n\t.reg .pred p;\n\t" \
        "mbarrier.try_wait.parity.acquire.cta.shared::cta.b64 p, [%1], %2;\n\t" \
        "selp.b32 %0, 1, 0, p;\n\t}" : "=r"(_done) : "r"(_mb), "r"(_p) : "memory"); \
    if (!_done){ \
        asm volatile("{\n\t.reg .pred P1;\n\t" \
            "WL_%=:\n\t" \
            "mbarrier.try_wait.parity.acquire.cta.shared::cta.b64 P1, [%0], %1, 0x989680;\n\t" \
            "@P1 bra.uni WD_%=;\n\t" \
            "bra.uni WL_%=;\n\t" \
            "WD_%=:\n\t}" :: "r"(_mb), "r"(_p) : "memory"); \
    } \
} while(0)

// one elected thread: expect_tx + 2 bulk copies (A tile, B tile) into a slot
__device__ __forceinline__ void issue_stage(uint32_t mbar, uint32_t sA,
                                            const char* gA, const char* gB){
    asm volatile("mbarrier.arrive.expect_tx.shared.b64 _, [%0], %1;"
        :: "r"(mbar), "r"((uint32_t)SLOT_B) : "memory");
    asm volatile("cp.async.bulk.shared::cluster.global.mbarrier::complete_tx::bytes [%0], [%1], %2, [%3];"
        :: "r"(sA), "l"(gA), "r"((uint32_t)A_TILE_B), "r"(mbar) : "memory");
    asm volatile("cp.async.bulk.shared::cluster.global.mbarrier::complete_tx::bytes [%0], [%1], %2, [%3];"
        :: "r"(sA + A_TILE_B), "l"(gB), "r"((uint32_t)B_TILE_B), "r"(mbar) : "memory");
}

__device__ __forceinline__ float sigf(float x){ return 1.f/(1.f + __expf(-x)); }
__device__ __forceinline__ float tanhf2(float x){ return 2.f/(1.f + __expf(-2.f*x)) - 1.f; }

// ---------------- step args ----------------
struct StepArgs {
    const char* A0;        // X' base for this t (or null), stage-major
    const char* A1;        // h' read pingpong base, stage-major
    const char* W;         // W' base, stage-major
    const float* bias;
    const float* r1w;      // [4096] decoder rank-1 weights or null
    const float* r1x;      // [NB] previous prediction or null
    float*  cbuf;          // [NB,NH] cell state in/out (linear)
    __half* dh;            // h' write pingpong base (stage-major, swizzled)
    float*  dhf;           // optional fp32 h out (linear)
    int K0, K1;
};

// ---------------- fused LSTM step kernel (256 threads, BM=32 tile) --------
__global__ void __launch_bounds__(256) lstm_step(StepArgs a){
    extern __shared__ char smc[];
    uint32_t sb = smem_u32(smc);
    const int tid  = threadIdx.x;
    const int warp = tid >> 5;
    const int l    = tid & 31;
    const int wm   = warp & 1;        // 2 M-warps (16 rows each)
    const int wn   = warp >> 1;       // 4 N-warps (16 gate-cols each)
    const int bx     = blockIdx.x;          // B block (64 gate-rows)
    const int m_base = blockIdx.y * BM;     // 8 M-blocks of 32 rows

    const int S0 = a.K0 >> 5;
    const int ns = (a.K0 + a.K1) >> 5;

    if (tid == 0){
#pragma unroll
        for (int q = 0; q < NSLOT; q++) MBARRIER_INIT(sb + q*8, 1);
    }
    __syncthreads();
    if (tid == 0){
#pragma unroll
        for (int s = 0; s < LEAD; s++){
            const char* gA = ((s < S0) ? a.A0 + (size_t)s*A_STG
                                       : a.A1 + (size_t)(s - S0)*A_STG) + m_base*64;
            const char* gB = a.W + (size_t)s*B_STG + (size_t)bx*B_TILE_B;
            issue_stage(sb + s*8, sb + SMEM_OFF + s*SLOT_B, gA, gB);
        }
    }

    float acc[2][4];
#pragma unroll
    for (int j=0;j<2;j++)
#pragma unroll
        for (int k=0;k<4;k++) acc[j][k] = 0.f;

    int rs = 0, rp = 0, ws = LEAD;
    for (int s = 0; s < ns; s++){
        __syncthreads();                       // slot-recycle guard
        if (tid == 0 && s + LEAD < ns){
            int ss = s + LEAD;
            const char* gA = ((ss < S0) ? a.A0 + (size_t)ss*A_STG
                                        : a.A1 + (size_t)(ss - S0)*A_STG) + m_base*64;
            const char* gB = a.W + (size_t)ss*B_STG + (size_t)bx*B_TILE_B;
            issue_stage(sb + ws*8, sb + SMEM_OFF + ws*SLOT_B, gA, gB);
        }
        MBARRIER_WAIT_PARITY(sb + rs*8, rp);   // stage s data ready

        uint32_t sA = sb + SMEM_OFF + rs*SLOT_B;
        uint32_t sB = sA + A_TILE_B;
#pragma unroll
        for (int kk = 0; kk < BK; kk += 16){
            uint32_t av[4], bv[2][2];
            {
                int row = wm*16 + (l & 15);
                uint32_t off = (uint32_t)row*64 + kk*2 + (l & 16);
                ldsm_x4(av[0], av[1], av[2], av[3], sA + swz64(off));
            }
            {
                int row = wn*16 + (l & 7) + ((l >> 4) & 1)*8;
                uint32_t off = (uint32_t)row*64 + kk*2 + ((l & 8) << 1);
                ldsm_x4(bv[0][0], bv[0][1], bv[1][0], bv[1][1], sB + swz64(off));
            }
#pragma unroll
            for (int fn = 0; fn < 2; fn++)
                mma16816(acc[fn], av[0],av[1],av[2],av[3], bv[fn][0], bv[fn][1]);
        }
        if (++rs == NSLOT){ rs = 0; rp ^= 1; }
        if (++ws == NSLOT) ws = 0;
    }

    // ---------------- epilogue: gates -> SMEM -> cell ----------------
    __syncthreads();
    float* sg = reinterpret_cast<float*>(smc + SMEM_OFF);   // [32][65] floats
    {
        const int rb = wm*16, cb = wn*16;
#pragma unroll
        for (int fn = 0; fn < 2; fn++){
            int r = rb + (l >> 2);
            int c = cb + fn*8  + (l & 3)*2;
            sg[r*65 + c]        = acc[fn][0];
            sg[r*65 + c + 1]    = acc[fn][1];
            sg[(r+8)*65 + c]    = acc[fn][2];
            sg[(r+8)*65 + c+1]  = acc[fn][3];
        }
    }
    __syncthreads();
    {
        const int u0 = bx * 16;                 // 16 hidden units per CTA
        const bool has_r1 = (a.r1w != nullptr);
        int m  = tid >> 3;                      // 32 rows, 8 threads each
        int ub = (tid & 7)*2;                   // 2 units per thread
        int mg = m_base + m;
        float p = has_r1 ? a.r1x[mg] : 0.f;
#pragma unroll
        for (int j = 0; j < 2; j++){
            int uu = ub + j;
            int ug = u0 + uu;
            float gi = sg[m*65 + uu]      + a.bias[ug];
            float gf = sg[m*65 + 16 + uu] + a.bias[NH + ug];
            float gg = sg[m*65 + 32 + uu] + a.bias[2*NH + ug];
            float go = sg[m*65 + 48 + uu] + a.bias[3*NH + ug];
            if (has_r1){
                gi += p*a.r1w[ug];        gf += p*a.r1w[NH + ug];
                gg += p*a.r1w[2*NH + ug]; go += p*a.r1w[3*NH + ug];
            }
            int ci = mg*NH + ug;
            float cn = sigf(gf)*a.cbuf[ci] + sigf(gi)*tanhf2(gg);
            float hv = sigf(go)*tanhf2(cn);
            a.cbuf[ci] = cn;
            // stage-major swizzled h' write: element (mg, ug) -> stage ug>>5
            int s_h = ug >> 5;
            int kcp = (ug & 31) ^ (((mg >> 1) & 3) << 3);
            a.dh[(size_t)(s_h*256 + mg)*32 + kcp] = __float2half(hv);
            if (a.dhf) a.dhf[ci] = hv;
        }
    }
}

// ---------------- fused setup: conversions into stage-major swizzled layouts
#define N_XH  (NS*NB*ND)
#define N_W0  (NG*1088)
#define N_W1  (NG*2048)
#define N_DW0 (NG*1024)
#define N_DW1 (NG*2048)
#define N_HZ  (4*BHE)
#define N_FZ  (2*BHE + NB)
#define N_TOTAL (N_XH + N_W0 + N_W1 + N_DW0 + N_DW1 + N_HZ + N_FZ)

// permuted W row p (0..4095): p = blk*64 + g*16 + j  <->  orig n = g*1024 + blk*16 + j
__device__ __forceinline__ int wrow_of_p(int p){
    int blk = p >> 6, g = (p >> 4) & 3, j = p & 15;
    return g*1024 + blk*16 + j;
}

__global__ void setup_all(
    const float* __restrict__ X,
    const float* __restrict__ eW0i, const float* __restrict__ eW0h,
    const float* __restrict__ eW1i, const float* __restrict__ eW1h,
    const float* __restrict__ dW0h,
    const float* __restrict__ dW1i, const float* __restrict__ dW1h,
    __half* __restrict__ Xh, __half* __restrict__ W0, __half* __restrict__ W1,
    __half* __restrict__ DW0, __half* __restrict__ DW1,
    __half* __restrict__ h0, __half* __restrict__ h1,
    float* __restrict__ c0, float* __restrict__ c1, float* __restrict__ pred)
{
    int i = blockIdx.x*256 + threadIdx.x;
    if (i >= N_TOTAL) return;
    if (i < N_XH){
        // X': [t][sk][b][32] swizzled
        int kcp = i & 31, b = (i >> 5) & 255, sk = (i >> 13) & 1, t = i >> 14;
        int kc = kcp ^ (((b >> 1) & 3) << 3);
        int d  = sk*32 + kc;
        Xh[i] = __float2half(X[((size_t)b << 14) + (t << 6) + d]);
        return;
    }
    i -= N_XH;
    if (i < N_W0){
        int kcp = i & 31, p = (i >> 5) & 4095, s = i >> 17;
        int kc = kcp ^ (((p >> 1) & 3) << 3);
        int n = wrow_of_p(p), k = s*32 + kc;
        float v = (k < 64) ? eW0i[n*64 + k] : eW0h[(size_t)n*1024 + (k - 64)];
        W0[i] = __float2half(v);
        return;
    }
    i -= N_W0;
    if (i < N_W1){
        int kcp = i & 31, p = (i >> 5) & 4095, s = i >> 17;
        int kc = kcp ^ (((p >> 1) & 3) << 3);
        int n = wrow_of_p(p), k = s*32 + kc;
        float v = (k < 1024) ? eW1i[(size_t)n*1024 + k] : eW1h[(size_t)n*1024 + (k - 1024)];
        W1[i] = __float2half(v);
        return;
    }
    i -= N_W1;
    if (i < N_DW0){
        int kcp = i & 31, p = (i >> 5) & 4095, s = i >> 17;
        int kc = kcp ^ (((p >> 1) & 3) << 3);
        int n = wrow_of_p(p), k = s*32 + kc;
        DW0[i] = __float2half(dW0h[(size_t)n*1024 + k]);
        return;
    }
    i -= N_DW0;
    if (i < N_DW1){
        int kcp = i & 31, p = (i >> 5) & 4095, s = i >> 17;
        int kc = kcp ^ (((p >> 1) & 3) << 3);
        int n = wrow_of_p(p), k = s*32 + kc;
        float v = (k < 1024) ? dW1i[(size_t)n*1024 + k] : dW1h[(size_t)n*1024 + (k - 1024)];
        DW1[i] = __float2half(v);
        return;
    }
    i -= N_DW1;
    if (i < N_HZ){
        if (i < 2*BHE) h0[i] = __float2half(0.f);
        else           h1[i - 2*BHE] = __float2half(0.f);
        return;
    }
    i -= N_HZ;
    if (i < BHE)            c0[i] = 0.f;
    else if (i < 2*BHE)     c1[i - BHE] = 0.f;
    else                    pred[i - 2*BHE] = 0.f;
}

__global__ void fc_kernel(const float* __restrict__ h1, const float* __restrict__ fcW,
                          const float* __restrict__ fcb, float* __restrict__ pred,
                          float* __restrict__ out, int t){
    __shared__ float red[4];
    int b = blockIdx.x, tid = threadIdx.x;
    float s = 0.f;
    for (int u = tid; u < NH; u += 128) s += h1[b*NH + u]*fcW[u];
#pragma unroll
    for (int o = 16; o; o >>= 1) s += __shfl_xor_sync(0xFFFFFFFFu, s, o);
    if ((tid & 31) == 0) red[tid >> 5] = s;
    __syncthreads();
    if (tid == 0){
        float v = red[0] + red[1] + red[2] + red[3] + fcb[0];
        pred[b] = v;
        out[b*NT + t] = v;
    }
}

// ---------------- host ----------------
extern "C" void kernel_launch(void* const* d_in, const int* in_sizes, int n_in,
                              void* d_out, int out_size){
    const float* X    = (const float*)d_in[0];
    const float* eW0i = (const float*)d_in[1];
    const float* eW0h = (const float*)d_in[2];
    const float* eb0  = (const float*)d_in[3];
    const float* eW1i = (const float*)d_in[4];
    const float* eW1h = (const float*)d_in[5];
    const float* eb1  = (const float*)d_in[6];
    const float* dW0i = (const float*)d_in[7];
    const float* dW0h = (const float*)d_in[8];
    const float* db0  = (const float*)d_in[9];
    const float* dW1i = (const float*)d_in[10];
    const float* dW1h = (const float*)d_in[11];
    const float* db1  = (const float*)d_in[12];
    const float* fcW  = (const float*)d_in[13];
    const float* fcb  = (const float*)d_in[14];
    float* out = (float*)d_out;

    __half *Xh, *W0, *W1, *DW0, *DW1, *h0, *h1;
    float *c0, *c1, *h1f, *pred;
    cudaGetSymbolAddress((void**)&Xh,  g_Xh);
    cudaGetSymbolAddress((void**)&W0,  g_W0);
    cudaGetSymbolAddress((void**)&W1,  g_W1);
    cudaGetSymbolAddress((void**)&DW0, g_DW0);
    cudaGetSymbolAddress((void**)&DW1, g_DW1);
    cudaGetSymbolAddress((void**)&h0,  g_h0);
    cudaGetSymbolAddress((void**)&h1,  g_h1);
    cudaGetSymbolAddress((void**)&c0,  g_c0);
    cudaGetSymbolAddress((void**)&c1,  g_c1);
    cudaGetSymbolAddress((void**)&h1f, g_h1f);
    cudaGetSymbolAddress((void**)&pred, g_pred);

    cudaFuncSetAttribute(lstm_step, cudaFuncAttributeMaxDynamicSharedMemorySize, SMEM_BYTES);

    setup_all<<<(N_TOTAL + 255)/256, 256>>>(
        X, eW0i, eW0h, eW1i, eW1h, dW0h, dW1i, dW1h,
        Xh, W0, W1, DW0, DW1, h0, h1, c0, c1, pred);

    dim3 grid(NG/BN, NB/BM);   // 64 x 8 = 512 CTAs -> 3-4 CTAs/SM

    // encoder: serial L0 / L1 per timestep (h' pingpong stride = BHE halves)
    for (int t = 0; t < NS; t++){
        int wr = t & 1, rd = wr ^ 1;
        StepArgs p0{};
        p0.A0 = (const char*)(Xh + (size_t)t*2*8192);       // 2 stages of X'
        p0.A1 = (const char*)(h0 + (size_t)rd*BHE);
        p0.W = (const char*)W0; p0.bias = eb0; p0.r1w = nullptr; p0.r1x = nullptr;
        p0.cbuf = c0; p0.dh = h0 + (size_t)wr*BHE; p0.dhf = nullptr;
        p0.K0 = ND; p0.K1 = NH;
        lstm_step<<<grid, 256, SMEM_BYTES>>>(p0);

        StepArgs p1{};
        p1.A0 = (const char*)(h0 + (size_t)wr*BHE);         // h0[t], 32 stages
        p1.A1 = (const char*)(h1 + (size_t)rd*BHE);
        p1.W = (const char*)W1; p1.bias = eb1; p1.r1w = nullptr; p1.r1x = nullptr;
        p1.cbuf = c1; p1.dh = h1 + (size_t)wr*BHE; p1.dhf = nullptr;
        p1.K0 = NH; p1.K1 = NH;
        lstm_step<<<grid, 256, SMEM_BYTES>>>(p1);
    }

    // decoder (encoder ended on parity 1 for both h0 and h1)
    for (int s = 0; s < NT; s++){
        int wr = s & 1, rd = wr ^ 1;
        StepArgs p0{};
        p0.A0 = nullptr;
        p0.A1 = (const char*)(h0 + (size_t)rd*BHE);
        p0.W = (const char*)DW0; p0.bias = db0; p0.r1w = dW0i; p0.r1x = pred;
        p0.cbuf = c0; p0.dh = h0 + (size_t)wr*BHE; p0.dhf = nullptr;
        p0.K0 = 0; p0.K1 = NH;
        lstm_step<<<grid, 256, SMEM_BYTES>>>(p0);

        StepArgs p1{};
        p1.A0 = (const char*)(h0 + (size_t)wr*BHE);
        p1.A1 = (const char*)(h1 + (size_t)rd*BHE);
        p1.W = (const char*)DW1; p1.bias = db1; p1.r1w = nullptr; p1.r1x = nullptr;
        p1.cbuf = c1; p1.dh = h1 + (size_t)wr*BHE; p1.dhf = h1f;
        p1.K0 = NH; p1.K1 = NH;
        lstm_step<<<grid, 256, SMEM_BYTES>>>(p1);

        fc_kernel<<<NB, 128>>>(h1f, fcW, fcb, pred, out, s);
    }
}

// round 17
// speedup vs baseline: 1.2640x; 1.2640x over previous
#include <cuda_runtime.h>
#include <cuda_fp16.h>
#include <cstdint>

// ---------------- problem dims ----------------
#define NB 256
#define NS 256
#define ND 64
#define NH 1024
#define NG 4096
#define NT 32
#define BHE (NB*NH)

// ---------------- GEMM tiling (BM=64, R14-proven; fused z=2 encoder) ------
#define BM 64
#define BN 64
#define BK 32                  // halves per stage; stage row = 64 bytes
#define NSLOT 6
#define LEAD 5
#define A_TILE_B 4096          // 64 rows x 64B
#define B_TILE_B 4096          // 64 rows x 64B
#define SLOT_B (A_TILE_B + B_TILE_B)   // 8192
#define SMEM_OFF 1024
#define SMEM_BYTES (SMEM_OFF + NSLOT*SLOT_B)   // 50176 -> 4 CTAs/SM by smem
#define A_STG 16384            // bytes per A' stage (256 rows x 64B)
#define B_STG 262144           // bytes per W' stage (4096 rows x 64B)

// ---------------- device scratch (stage-major, swizzled layouts) ----------
// A'/W' layout: [stage][row][32 halves], row = 64B, swizzle SW64 baked in.
__device__ __align__(128) __half g_Xh [NS*NB*ND];          // X': [t][2][256][32]
__device__ __align__(128) __half g_W0 [(size_t)NG*1088];   // W0': [34][4096][32]
__device__ __align__(128) __half g_W1 [(size_t)NG*2048];   // W1': [64][4096][32]
__device__ __align__(128) __half g_DW0[(size_t)NG*1024];   // DW0': [32][4096][32]
__device__ __align__(128) __half g_DW1[(size_t)NG*2048];   // DW1': [64][4096][32]
__device__ __align__(128) __half g_h0 [2*BHE];             // h0': pingpong [32][256][32]
__device__ __align__(128) __half g_h1 [2*BHE];
__device__ __align__(128) float  g_c0 [BHE];
__device__ __align__(128) float  g_c1 [BHE];
__device__ __align__(128) float  g_h1f[BHE];               // fp32 h1 (linear) for fc
__device__ __align__(128) float  g_pred[NB];

// ---------------- PTX helpers ----------------
__device__ __forceinline__ uint32_t smem_u32(const void* p){
    return (uint32_t)__cvta_generic_to_shared(p);
}
__device__ __forceinline__ uint32_t swz64(uint32_t off){   // SW64: XOR bits[5:4] by bits[8:7]
    return off ^ ((off >> 3) & 0x30);
}
__device__ __forceinline__ void ldsm_x4(uint32_t&r0,uint32_t&r1,uint32_t&r2,uint32_t&r3,uint32_t a){
    asm volatile("ldmatrix.sync.aligned.m8n8.x4.shared.b16 {%0,%1,%2,%3},[%4];\n"
        : "=r"(r0),"=r"(r1),"=r"(r2),"=r"(r3) : "r"(a));
}
__device__ __forceinline__ void mma16816(float* c,
    uint32_t a0,uint32_t a1,uint32_t a2,uint32_t a3,uint32_t b0,uint32_t b1){
    asm volatile("mma.sync.aligned.m16n8k16.row.col.f32.f16.f16.f32 "
        "{%0,%1,%2,%3},{%4,%5,%6,%7},{%8,%9},{%0,%1,%2,%3};\n"
        : "+f"(c[0]),"+f"(c[1]),"+f"(c[2]),"+f"(c[3])
        : "r"(a0),"r"(a1),"r"(a2),"r"(a3),"r"(b0),"r"(b1));
}
#define MBARRIER_INIT(addr, cnt) \
    asm volatile("mbarrier.init.shared.b64 [%0], %1;" :: "r"((uint32_t)(addr)), "r"((uint32_t)(cnt)) : "memory")
#define MBARRIER_WAIT_PARITY(addr, par) do { \
    uint32_t _mb = (uint32_t)(addr); uint32_t _p = (uint32_t)(par); uint32_t _done; \
    asm volatile("{\n\t.reg .pred p;\n\t" \
        "mbarrier.try_wait.parity.acquire.cta.shared::cta.b64 p, [%1], %2;\n\t" \
        "selp.b32 %0, 1, 0, p;\n\t}" : "=r"(_done) : "r"(_mb), "r"(_p) : "memory"); \
    if (!_done){ \
        asm volatile("{\n\t.reg .pred P1;\n\t" \
            "WL_%=:\n\t" \
            "mbarrier.try_wait.parity.acquire.cta.shared::cta.b64 P1, [%0], %1, 0x989680;\n\t" \
            "@P1 bra.uni WD_%=;\n\t" \
            "bra.uni WL_%=;\n\t" \
            "WD_%=:\n\t}" :: "r"(_mb), "r"(_p) : "memory"); \
    } \
} while(0)

// one elected thread: expect_tx + 2 bulk copies (A tile, B tile) into a slot
__device__ __forceinline__ void issue_stage(uint32_t mbar, uint32_t sA,
                                            const char* gA, const char* gB){
    asm volatile("mbarrier.arrive.expect_tx.shared.b64 _, [%0], %1;"
        :: "r"(mbar), "r"((uint32_t)SLOT_B) : "memory");
    asm volatile("cp.async.bulk.shared::cluster.global.mbarrier::complete_tx::bytes [%0], [%1], %2, [%3];"
        :: "r"(sA), "l"(gA), "r"((uint32_t)A_TILE_B), "r"(mbar) : "memory");
    asm volatile("cp.async.bulk.shared::cluster.global.mbarrier::complete_tx::bytes [%0], [%1], %2, [%3];"
        :: "r"(sA + A_TILE_B), "l"(gB), "r"((uint32_t)B_TILE_B), "r"(mbar) : "memory");
}

__device__ __forceinline__ float sigf(float x){ return 1.f/(1.f + __expf(-x)); }
__device__ __forceinline__ float tanhf2(float x){ return 2.f/(1.f + __expf(-2.f*x)) - 1.f; }

// ---------------- step args ----------------
struct StepArgs {
    const char* A0;        // X' base for this t (or null), stage-major
    const char* A1;        // h' read pingpong base, stage-major
    const char* W;         // W' base, stage-major
    const float* bias;
    const float* r1w;      // [4096] decoder rank-1 weights or null
    const float* r1x;      // [NB] previous prediction or null
    float*  cbuf;          // [NB,NH] cell state in/out (linear)
    __half* dh;            // h' write pingpong base (stage-major, swizzled)
    float*  dhf;           // optional fp32 h out (linear)
    int K0, K1;
};

// ---------------- fused LSTM step kernel (256 threads, BM=64 tile) --------
// blockIdx.z selects which of two independent layer-steps this CTA computes.
__global__ void __launch_bounds__(256) lstm_step(StepArgs pa, StepArgs pb){
    StepArgs a = (blockIdx.z == 0) ? pa : pb;
    if (a.W == nullptr) return;
    extern __shared__ char smc[];
    uint32_t sb = smem_u32(smc);
    const int tid  = threadIdx.x;
    const int warp = tid >> 5;
    const int l    = tid & 31;
    const int wm   = warp & 3;        // 4 M-warps (16 rows each)
    const int wn   = warp >> 2;       // 2 N-warps (32 gate-cols each)
    const int bx     = blockIdx.x;          // B block (64 gate-rows)
    const int m_base = blockIdx.y * BM;     // 4 M-blocks of 64 rows

    const int S0 = a.K0 >> 5;
    const int ns = (a.K0 + a.K1) >> 5;

    if (tid == 0){
#pragma unroll
        for (int q = 0; q < NSLOT; q++) MBARRIER_INIT(sb + q*8, 1);
    }
    __syncthreads();
    if (tid == 0){
#pragma unroll
        for (int s = 0; s < LEAD; s++){
            const char* gA = ((s < S0) ? a.A0 + (size_t)s*A_STG
                                       : a.A1 + (size_t)(s - S0)*A_STG) + m_base*64;
            const char* gB = a.W + (size_t)s*B_STG + (size_t)bx*B_TILE_B;
            issue_stage(sb + s*8, sb + SMEM_OFF + s*SLOT_B, gA, gB);
        }
    }

    float acc[4][4];
#pragma unroll
    for (int j=0;j<4;j++)
#pragma unroll
        for (int k=0;k<4;k++) acc[j][k] = 0.f;

    int rs = 0, rp = 0, ws = LEAD;
    for (int s = 0; s < ns; s++){
        __syncthreads();                       // slot-recycle guard
        if (tid == 0 && s + LEAD < ns){
            int ss = s + LEAD;
            const char* gA = ((ss < S0) ? a.A0 + (size_t)ss*A_STG
                                        : a.A1 + (size_t)(ss - S0)*A_STG) + m_base*64;
            const char* gB = a.W + (size_t)ss*B_STG + (size_t)bx*B_TILE_B;
            issue_stage(sb + ws*8, sb + SMEM_OFF + ws*SLOT_B, gA, gB);
        }
        MBARRIER_WAIT_PARITY(sb + rs*8, rp);   // stage s data ready

        uint32_t sA = sb + SMEM_OFF + rs*SLOT_B;
        uint32_t sB = sA + A_TILE_B;
#pragma unroll
        for (int kk = 0; kk < BK; kk += 16){
            uint32_t av[4], bv[4][2];
            {
                int row = wm*16 + (l & 15);
                uint32_t off = (uint32_t)row*64 + kk*2 + (l & 16);
                ldsm_x4(av[0], av[1], av[2], av[3], sA + swz64(off));
            }
#pragma unroll
            for (int nh = 0; nh < 2; nh++){
                int row = wn*32 + nh*16 + (l & 7) + ((l >> 4) & 1)*8;
                uint32_t off = (uint32_t)row*64 + kk*2 + ((l & 8) << 1);
                ldsm_x4(bv[2*nh][0], bv[2*nh][1], bv[2*nh+1][0], bv[2*nh+1][1], sB + swz64(off));
            }
#pragma unroll
            for (int fn = 0; fn < 4; fn++)
                mma16816(acc[fn], av[0],av[1],av[2],av[3], bv[fn][0], bv[fn][1]);
        }
        if (++rs == NSLOT){ rs = 0; rp ^= 1; }
        if (++ws == NSLOT) ws = 0;
    }

    // ---------------- epilogue: gates -> SMEM -> cell ----------------
    __syncthreads();
    float* sg = reinterpret_cast<float*>(smc + SMEM_OFF);   // [64][65] floats
    {
        const int rb = wm*16, cb = wn*32;
#pragma unroll
        for (int fn = 0; fn < 4; fn++){
            int r = rb + (l >> 2);
            int c = cb + fn*8  + (l & 3)*2;
            sg[r*65 + c]        = acc[fn][0];
            sg[r*65 + c + 1]    = acc[fn][1];
            sg[(r+8)*65 + c]    = acc[fn][2];
            sg[(r+8)*65 + c+1]  = acc[fn][3];
        }
    }
    __syncthreads();
    {
        const int u0 = bx * 16;                 // 16 hidden units per CTA
        const bool has_r1 = (a.r1w != nullptr);
        int m  = tid >> 2;                      // 64 rows, 4 threads each
        int ub = (tid & 3)*4;                   // 4 units per thread
        int mg = m_base + m;
        float p = has_r1 ? a.r1x[mg] : 0.f;
#pragma unroll
        for (int j = 0; j < 4; j++){
            int uu = ub + j;
            int ug = u0 + uu;
            float gi = sg[m*65 + uu]      + a.bias[ug];
            float gf = sg[m*65 + 16 + uu] + a.bias[NH + ug];
            float gg = sg[m*65 + 32 + uu] + a.bias[2*NH + ug];
            float go = sg[m*65 + 48 + uu] + a.bias[3*NH + ug];
            if (has_r1){
                gi += p*a.r1w[ug];        gf += p*a.r1w[NH + ug];
                gg += p*a.r1w[2*NH + ug]; go += p*a.r1w[3*NH + ug];
            }
            int ci = mg*NH + ug;
            float cn = sigf(gf)*a.cbuf[ci] + sigf(gi)*tanhf2(gg);
            float hv = sigf(go)*tanhf2(cn);
            a.cbuf[ci] = cn;
            // stage-major swizzled h' write: element (mg, ug) -> stage ug>>5
            int s_h = ug >> 5;
            int kcp = (ug & 31) ^ (((mg >> 1) & 3) << 3);
            a.dh[(size_t)(s_h*256 + mg)*32 + kcp] = __float2half(hv);
            if (a.dhf) a.dhf[ci] = hv;
        }
    }
}

// ---------------- fused setup: conversions into stage-major swizzled layouts
#define N_XH  (NS*NB*ND)
#define N_W0  (NG*1088)
#define N_W1  (NG*2048)
#define N_DW0 (NG*1024)
#define N_DW1 (NG*2048)
#define N_HZ  (4*BHE)
#define N_FZ  (2*BHE + NB)
#define N_TOTAL (N_XH + N_W0 + N_W1 + N_DW0 + N_DW1 + N_HZ + N_FZ)

// permuted W row p (0..4095): p = blk*64 + g*16 + j  <->  orig n = g*1024 + blk*16 + j
__device__ __forceinline__ int wrow_of_p(int p){
    int blk = p >> 6, g = (p >> 4) & 3, j = p & 15;
    return g*1024 + blk*16 + j;
}

__global__ void setup_all(
    const float* __restrict__ X,
    const float* __restrict__ eW0i, const float* __restrict__ eW0h,
    const float* __restrict__ eW1i, const float* __restrict__ eW1h,
    const float* __restrict__ dW0h,
    const float* __restrict__ dW1i, const float* __restrict__ dW1h,
    __half* __restrict__ Xh, __half* __restrict__ W0, __half* __restrict__ W1,
    __half* __restrict__ DW0, __half* __restrict__ DW1,
    __half* __restrict__ h0, __half* __restrict__ h1,
    float* __restrict__ c0, float* __restrict__ c1, float* __restrict__ pred)
{
    int i = blockIdx.x*256 + threadIdx.x;
    if (i >= N_TOTAL) return;
    if (i < N_XH){
        // X': [t][sk][b][32] swizzled
        int kcp = i & 31, b = (i >> 5) & 255, sk = (i >> 13) & 1, t = i >> 14;
        int kc = kcp ^ (((b >> 1) & 3) << 3);
        int d  = sk*32 + kc;
        Xh[i] = __float2half(X[((size_t)b << 14) + (t << 6) + d]);
        return;
    }
    i -= N_XH;
    if (i < N_W0){
        int kcp = i & 31, p = (i >> 5) & 4095, s = i >> 17;
        int kc = kcp ^ (((p >> 1) & 3) << 3);
        int n = wrow_of_p(p), k = s*32 + kc;
        float v = (k < 64) ? eW0i[n*64 + k] : eW0h[(size_t)n*1024 + (k - 64)];
        W0[i] = __float2half(v);
        return;
    }
    i -= N_W0;
    if (i < N_W1){
        int kcp = i & 31, p = (i >> 5) & 4095, s = i >> 17;
        int kc = kcp ^ (((p >> 1) & 3) << 3);
        int n = wrow_of_p(p), k = s*32 + kc;
        float v = (k < 1024) ? eW1i[(size_t)n*1024 + k] : eW1h[(size_t)n*1024 + (k - 1024)];
        W1[i] = __float2half(v);
        return;
    }
    i -= N_W1;
    if (i < N_DW0){
        int kcp = i & 31, p = (i >> 5) & 4095, s = i >> 17;
        int kc = kcp ^ (((p >> 1) & 3) << 3);
        int n = wrow_of_p(p), k = s*32 + kc;
        DW0[i] = __float2half(dW0h[(size_t)n*1024 + k]);
        return;
    }
    i -= N_DW0;
    if (i < N_DW1){
        int kcp = i & 31, p = (i >> 5) & 4095, s = i >> 17;
        int kc = kcp ^ (((p >> 1) & 3) << 3);
        int n = wrow_of_p(p), k = s*32 + kc;
        float v = (k < 1024) ? dW1i[(size_t)n*1024 + k] : dW1h[(size_t)n*1024 + (k - 1024)];
        DW1[i] = __float2half(v);
        return;
    }
    i -= N_DW1;
    if (i < N_HZ){
        if (i < 2*BHE) h0[i] = __float2half(0.f);
        else           h1[i - 2*BHE] = __float2half(0.f);
        return;
    }
    i -= N_HZ;
    if (i < BHE)            c0[i] = 0.f;
    else if (i < 2*BHE)     c1[i - BHE] = 0.f;
    else                    pred[i - 2*BHE] = 0.f;
}

__global__ void fc_kernel(const float* __restrict__ h1, const float* __restrict__ fcW,
                          const float* __restrict__ fcb, float* __restrict__ pred,
                          float* __restrict__ out, int t){
    __shared__ float red[4];
    int b = blockIdx.x, tid = threadIdx.x;
    float s = 0.f;
    for (int u = tid; u < NH; u += 128) s += h1[b*NH + u]*fcW[u];
#pragma unroll
    for (int o = 16; o; o >>= 1) s += __shfl_xor_sync(0xFFFFFFFFu, s, o);
    if ((tid & 31) == 0) red[tid >> 5] = s;
    __syncthreads();
    if (tid == 0){
        float v = red[0] + red[1] + red[2] + red[3] + fcb[0];
        pred[b] = v;
        out[b*NT + t] = v;
    }
}

// ---------------- host ----------------
extern "C" void kernel_launch(void* const* d_in, const int* in_sizes, int n_in,
                              void* d_out, int out_size){
    const float* X    = (const float*)d_in[0];
    const float* eW0i = (const float*)d_in[1];
    const float* eW0h = (const float*)d_in[2];
    const float* eb0  = (const float*)d_in[3];
    const float* eW1i = (const float*)d_in[4];
    const float* eW1h = (const float*)d_in[5];
    const float* eb1  = (const float*)d_in[6];
    const float* dW0i = (const float*)d_in[7];
    const float* dW0h = (const float*)d_in[8];
    const float* db0  = (const float*)d_in[9];
    const float* dW1i = (const float*)d_in[10];
    const float* dW1h = (const float*)d_in[11];
    const float* db1  = (const float*)d_in[12];
    const float* fcW  = (const float*)d_in[13];
    const float* fcb  = (const float*)d_in[14];
    float* out = (float*)d_out;

    __half *Xh, *W0, *W1, *DW0, *DW1, *h0, *h1;
    float *c0, *c1, *h1f, *pred;
    cudaGetSymbolAddress((void**)&Xh,  g_Xh);
    cudaGetSymbolAddress((void**)&W0,  g_W0);
    cudaGetSymbolAddress((void**)&W1,  g_W1);
    cudaGetSymbolAddress((void**)&DW0, g_DW0);
    cudaGetSymbolAddress((void**)&DW1, g_DW1);
    cudaGetSymbolAddress((void**)&h0,  g_h0);
    cudaGetSymbolAddress((void**)&h1,  g_h1);
    cudaGetSymbolAddress((void**)&c0,  g_c0);
    cudaGetSymbolAddress((void**)&c1,  g_c1);
    cudaGetSymbolAddress((void**)&h1f, g_h1f);
    cudaGetSymbolAddress((void**)&pred, g_pred);

    cudaFuncSetAttribute(lstm_step, cudaFuncAttributeMaxDynamicSharedMemorySize, SMEM_BYTES);

    setup_all<<<(N_TOTAL + 255)/256, 256>>>(
        X, eW0i, eW0h, eW1i, eW1h, dW0h, dW1i, dW1h,
        Xh, W0, W1, DW0, DW1, h0, h1, c0, c1, pred);

    StepArgs zz{}; zz.W = nullptr;
    dim3 grid2(NG/BN, NB/BM, 2);   // 64 x 4 x 2 = 512 CTAs, one wave @4 CTAs/SM
    dim3 grid1(NG/BN, NB/BM, 1);   // 256 CTAs

    // encoder: launch t computes L0(t) || L1(t-1)  (layer pipeline, R10 dataflow)
    for (int t = 0; t <= NS; t++){
        StepArgs p0 = zz, p1 = zz;
        if (t < NS){
            int wr = t & 1, rd = wr ^ 1;
            p0.A0 = (const char*)(Xh + (size_t)t*2*8192);   // 2 stages of X'
            p0.A1 = (const char*)(h0 + (size_t)rd*BHE);
            p0.W = (const char*)W0; p0.bias = eb0;
            p0.cbuf = c0; p0.dh = h0 + (size_t)wr*BHE;
            p0.K0 = ND; p0.K1 = NH;
        }
        if (t >= 1){
            int u = t - 1, wr = u & 1, rd = wr ^ 1;
            p1.A0 = (const char*)(h0 + (size_t)wr*BHE);     // h0[u] (written last launch)
            p1.A1 = (const char*)(h1 + (size_t)rd*BHE);     // h1[u-1]
            p1.W = (const char*)W1; p1.bias = eb1;
            p1.cbuf = c1; p1.dh = h1 + (size_t)wr*BHE;
            p1.K0 = NH; p1.K1 = NH;
        }
        lstm_step<<<grid2, 256, SMEM_BYTES>>>(p0, p1);
    }

    // decoder (encoder ended on parity 1 for both h0 and h1); strictly serial
    for (int s = 0; s < NT; s++){
        int wr = s & 1, rd = wr ^ 1;
        StepArgs p0 = zz;
        p0.A0 = nullptr;
        p0.A1 = (const char*)(h0 + (size_t)rd*BHE);
        p0.W = (const char*)DW0; p0.bias = db0; p0.r1w = dW0i; p0.r1x = pred;
        p0.cbuf = c0; p0.dh = h0 + (size_t)wr*BHE;
        p0.K0 = 0; p0.K1 = NH;
        lstm_step<<<grid1, 256, SMEM_BYTES>>>(p0, zz);

        StepArgs p1 = zz;
        p1.A0 = (const char*)(h0 + (size_t)wr*BHE);
        p1.A1 = (const char*)(h1 + (size_t)rd*BHE);
        p1.W = (const char*)DW1; p1.bias = db1;
        p1.cbuf = c1; p1.dh = h1 + (size_t)wr*BHE; p1.dhf = h1f;
        p1.K0 = NH; p1.K1 = NH;
        lstm_step<<<grid1, 256, SMEM_BYTES>>>(p1, zz);

        fc_kernel<<<NB, 128>>>(h1f, fcW, fcb, pred, out, s);
    }
}